// round 1
// baseline (speedup 1.0000x reference)
#include <cuda_runtime.h>
#include <math.h>

#define D_HALF   512
#define NPOS     8192
#define SPINE_N  10

// 16 MiB lattice-encoding lookup table: lat_enc row per distinct position.
__device__ float g_lut[NPOS * D_HALF];

__constant__ int c_spine[SPINE_N] = {0, 2, 4, 12, 36, 104, 304, 888, 2592, 7568};

// One block per position: feats -> Linear(3,512) -> LayerNorm -> exact GELU.
__global__ void __launch_bounds__(128) lut_kernel(
    const float* __restrict__ W1,     // [512, 3] row-major
    const float* __restrict__ b1,     // [512]
    const float* __restrict__ gamma,  // [512]
    const float* __restrict__ beta)   // [512]
{
    const int pos = blockIdx.x;
    const int tid = threadIdx.x;  // 128 threads, 4 dims each

    // level = #spine entries <= pos (searchsorted right); spine[0]==0 -> level >= 1
    int level = 0;
#pragma unroll
    for (int i = 0; i < SPINE_N; i++) level += (c_spine[i] <= pos) ? 1 : 0;
    const float left  = (float)(pos - c_spine[level - 1]);
    const float right = (level < SPINE_N) ? (float)(c_spine[level] - pos) : 0.0f;
    const float lv    = (float)level;

    float h[4];
    float lsum = 0.0f;
#pragma unroll
    for (int k = 0; k < 4; k++) {
        const int d = tid + k * 128;
        h[k] = fmaf(W1[d * 3 + 0], left,
               fmaf(W1[d * 3 + 1], right,
               fmaf(W1[d * 3 + 2], lv, b1[d])));
        lsum += h[k];
    }

    __shared__ float sred[4];
    // block-reduce sum for mean
#pragma unroll
    for (int o = 16; o > 0; o >>= 1) lsum += __shfl_down_sync(0xffffffffu, lsum, o);
    if ((tid & 31) == 0) sred[tid >> 5] = lsum;
    __syncthreads();
    const float mu = (sred[0] + sred[1] + sred[2] + sred[3]) * (1.0f / (float)D_HALF);

    // two-pass variance (matches reference: mean of (h-mu)^2)
    float vs = 0.0f;
#pragma unroll
    for (int k = 0; k < 4; k++) { const float d = h[k] - mu; vs = fmaf(d, d, vs); }
    __syncthreads();  // protect sred reuse
#pragma unroll
    for (int o = 16; o > 0; o >>= 1) vs += __shfl_down_sync(0xffffffffu, vs, o);
    if ((tid & 31) == 0) sred[tid >> 5] = vs;
    __syncthreads();
    const float var  = (sred[0] + sred[1] + sred[2] + sred[3]) * (1.0f / (float)D_HALF);
    const float rstd = rsqrtf(var + 1e-5f);

#pragma unroll
    for (int k = 0; k < 4; k++) {
        const int d = tid + k * 128;
        const float x = fmaf((h[k] - mu) * rstd, gamma[d], beta[d]);
        // exact GELU: x * 0.5 * (1 + erf(x / sqrt(2)))
        const float g = 0.5f * x * (1.0f + erff(x * 0.70710678118654752440f));
        g_lut[pos * D_HALF + d] = g;
    }
}

// One warp per token: concat(pe[pos], lut[pos]) -> out row (4 KB), float4 coalesced.
__global__ void __launch_bounds__(256) gather_kernel(
    const int*    __restrict__ positions,
    const float4* __restrict__ pe4,   // [NPOS, 128] float4
    float4*       __restrict__ out4,  // [ntok, 256] float4
    int ntok)
{
    const int warp = (int)((blockIdx.x * blockDim.x + threadIdx.x) >> 5);
    const int lane = threadIdx.x & 31;
    if (warp >= ntok) return;

    const int pos = __ldg(&positions[warp]);  // warp-uniform broadcast

    const float4* __restrict__ src = pe4 + (size_t)pos * 128;
    const float4* __restrict__ lut = ((const float4*)g_lut) + (size_t)pos * 128;
    float4* __restrict__ dst = out4 + (size_t)warp * 256;

    // Front-batch all 8 independent 16B loads for MLP, then store.
    float4 v[8];
#pragma unroll
    for (int i = 0; i < 4; i++) v[i]     = __ldg(&src[i * 32 + lane]);
#pragma unroll
    for (int i = 0; i < 4; i++) v[4 + i] = __ldg(&lut[i * 32 + lane]);
#pragma unroll
    for (int i = 0; i < 4; i++) dst[i * 32 + lane]       = v[i];
#pragma unroll
    for (int i = 0; i < 4; i++) dst[128 + i * 32 + lane] = v[4 + i];
}

extern "C" void kernel_launch(void* const* d_in, const int* in_sizes, int n_in,
                              void* d_out, int out_size)
{
    const int*   positions = (const int*)  d_in[0];
    const float* pe        = (const float*)d_in[1];
    const float* W1        = (const float*)d_in[2];
    const float* b1        = (const float*)d_in[3];
    const float* ln_gamma  = (const float*)d_in[4];
    const float* ln_beta   = (const float*)d_in[5];
    float* out = (float*)d_out;

    const int ntok = in_sizes[0];  // B*S = 131072

    lut_kernel<<<NPOS, 128>>>(W1, b1, ln_gamma, ln_beta);

    const int threads = 256;                       // 8 warps/block, 1 token/warp
    const int blocks  = (ntok * 32 + threads - 1) / threads;
    gather_kernel<<<blocks, threads>>>(positions, (const float4*)pe, (float4*)out, ntok);
}

// round 3
// speedup vs baseline: 1.1318x; 1.1318x over previous
#include <cuda_runtime.h>
#include <math.h>

#define D_HALF   512
#define NPOS     8192
#define SPINE_N  10

// 16 MiB lattice-encoding lookup table: lat_enc row per distinct position.
__device__ float g_lut[NPOS * D_HALF];

__constant__ int c_spine[SPINE_N] = {0, 2, 4, 12, 36, 104, 304, 888, 2592, 7568};

// One WARP per position: feats -> Linear(3,512) -> LayerNorm -> exact GELU.
// 16 dims per lane, warp-shuffle reductions only (no smem, no block barriers).
__global__ void __launch_bounds__(256) lut_kernel(
    const float* __restrict__ W1,     // [512, 3] row-major
    const float* __restrict__ b1,     // [512]
    const float* __restrict__ gamma,  // [512]
    const float* __restrict__ beta)   // [512]
{
    const int warp = (int)((blockIdx.x * blockDim.x + threadIdx.x) >> 5);
    const int lane = threadIdx.x & 31;
    const int pos  = warp;
    if (pos >= NPOS) return;

    // level = #spine entries <= pos (searchsorted right); spine[0]==0 -> level >= 1
    int level = 0;
#pragma unroll
    for (int i = 0; i < SPINE_N; i++) level += (c_spine[i] <= pos) ? 1 : 0;
    const float left  = (float)(pos - c_spine[level - 1]);
    const float right = (level < SPINE_N) ? (float)(c_spine[level] - pos) : 0.0f;
    const float lv    = (float)level;

    // Each lane owns dims d = lane + k*32, k = 0..15
    float h[16];
    float lsum = 0.0f;
#pragma unroll
    for (int k = 0; k < 16; k++) {
        const int d = lane + k * 32;
        h[k] = fmaf(__ldg(&W1[d * 3 + 0]), left,
               fmaf(__ldg(&W1[d * 3 + 1]), right,
               fmaf(__ldg(&W1[d * 3 + 2]), lv, __ldg(&b1[d]))));
        lsum += h[k];
    }
    // warp all-reduce (butterfly) for mean
#pragma unroll
    for (int o = 16; o > 0; o >>= 1) lsum += __shfl_xor_sync(0xffffffffu, lsum, o);
    const float mu = lsum * (1.0f / (float)D_HALF);

    float vs = 0.0f;
#pragma unroll
    for (int k = 0; k < 16; k++) { const float dd = h[k] - mu; vs = fmaf(dd, dd, vs); }
#pragma unroll
    for (int o = 16; o > 0; o >>= 1) vs += __shfl_xor_sync(0xffffffffu, vs, o);
    const float var  = vs * (1.0f / (float)D_HALF);
    const float rstd = rsqrtf(var + 1e-5f);

#pragma unroll
    for (int k = 0; k < 16; k++) {
        const int d = lane + k * 32;
        const float x = fmaf((h[k] - mu) * rstd, __ldg(&gamma[d]), __ldg(&beta[d]));
        // exact GELU: x * 0.5 * (1 + erf(x / sqrt(2)))
        g_lut[pos * D_HALF + d] = 0.5f * x * (1.0f + erff(x * 0.70710678118654752440f));
    }
}

// One warp per token: concat(pe[pos], lut[pos]) -> out row (4 KB).
// Table reads cached (L2-resident); output stores STREAMING (__stcs) so the
// 512 MiB write stream does not evict the 32 MiB of tables from L2.
__global__ void __launch_bounds__(256) gather_kernel(
    const int*    __restrict__ positions,
    const float4* __restrict__ pe4,   // [NPOS, 128] float4
    float4*       __restrict__ out4,  // [ntok, 256] float4
    int ntok)
{
    const int warp = (int)((blockIdx.x * blockDim.x + threadIdx.x) >> 5);
    const int lane = threadIdx.x & 31;
    if (warp >= ntok) return;

    const int pos = __ldg(&positions[warp]);  // warp-uniform broadcast

    const float4* __restrict__ src = pe4 + (size_t)pos * 128;
    const float4* __restrict__ lut = ((const float4*)g_lut) + (size_t)pos * 128;
    float4* __restrict__ dst = out4 + (size_t)warp * 256;

    // Front-batch all 8 independent 16B loads for MLP, then stream out.
    float4 v[8];
#pragma unroll
    for (int i = 0; i < 4; i++) v[i]     = __ldg(&src[i * 32 + lane]);
#pragma unroll
    for (int i = 0; i < 4; i++) v[4 + i] = __ldg(&lut[i * 32 + lane]);
#pragma unroll
    for (int i = 0; i < 4; i++) __stcs(&dst[i * 32 + lane],       v[i]);
#pragma unroll
    for (int i = 0; i < 4; i++) __stcs(&dst[128 + i * 32 + lane], v[4 + i]);
}

extern "C" void kernel_launch(void* const* d_in, const int* in_sizes, int n_in,
                              void* d_out, int out_size)
{
    const int*   positions = (const int*)  d_in[0];
    const float* pe        = (const float*)d_in[1];
    const float* W1        = (const float*)d_in[2];
    const float* b1        = (const float*)d_in[3];
    const float* ln_gamma  = (const float*)d_in[4];
    const float* ln_beta   = (const float*)d_in[5];
    float* out = (float*)d_out;

    const int ntok = in_sizes[0];  // B*S = 131072

    // 8 warps/block, one position per warp
    lut_kernel<<<(NPOS * 32) / 256, 256>>>(W1, b1, ln_gamma, ln_beta);

    const int threads = 256;  // 8 warps/block, 1 token/warp
    const int blocks  = (ntok * 32 + threads - 1) / threads;
    gather_kernel<<<blocks, threads>>>(positions, (const float4*)pe, (float4*)out, ntok);
}

// round 4
// speedup vs baseline: 1.1322x; 1.0003x over previous
#include <cuda_runtime.h>
#include <math.h>

#define D_HALF   512
#define NPOS     8192
#define SPINE_N  10
#define MAX_TOK  131072

__constant__ int c_spine[SPINE_N] = {0, 2, 4, 12, 36, 104, 304, 888, 2592, 7568};

// Scratch for position-bucketing (device globals: no allocation allowed).
__device__ int g_count[NPOS];
__device__ int g_offset[NPOS];
__device__ int g_cursor[NPOS];
__device__ int g_bucket[MAX_TOK];

// ---------------------------------------------------------------- prep passes
__global__ void zero_kernel() {
    const int i = blockIdx.x * blockDim.x + threadIdx.x;
    if (i < NPOS) { g_count[i] = 0; g_cursor[i] = 0; }
}

__global__ void hist_kernel(const int* __restrict__ positions, int ntok) {
    const int i = blockIdx.x * blockDim.x + threadIdx.x;
    if (i < ntok) atomicAdd(&g_count[positions[i]], 1);
}

// Single-block exclusive prefix scan over 8192 counts (1024 thr, 8 elems each).
__global__ void __launch_bounds__(1024) scan_kernel() {
    __shared__ int ssum[1024];
    const int t = threadIdx.x;
    const int base = t * 8;
    int c[8];
    int s = 0;
#pragma unroll
    for (int k = 0; k < 8; k++) { c[k] = g_count[base + k]; s += c[k]; }
    ssum[t] = s;
    __syncthreads();
    // Hillis-Steele inclusive scan
    for (int off = 1; off < 1024; off <<= 1) {
        int v = (t >= off) ? ssum[t - off] : 0;
        __syncthreads();
        ssum[t] += v;
        __syncthreads();
    }
    int run = (t == 0) ? 0 : ssum[t - 1];  // exclusive base
#pragma unroll
    for (int k = 0; k < 8; k++) { g_offset[base + k] = run; run += c[k]; }
}

__global__ void scatter_kernel(const int* __restrict__ positions, int ntok) {
    const int i = blockIdx.x * blockDim.x + threadIdx.x;
    if (i < ntok) {
        const int pos  = positions[i];
        const int slot = atomicAdd(&g_cursor[pos], 1);
        g_bucket[g_offset[pos] + slot] = i;
    }
}

// ------------------------------------------------------------- main kernel
// One block per position: compute lat-enc row ONCE in registers
// (Linear(3,512) -> LayerNorm -> exact GELU), load pe row once, then stream
// the concatenated 4 KB row to every token holding this position.
__global__ void __launch_bounds__(128) gather_kernel(
    const float4* __restrict__ pe4,    // [NPOS, 128] float4
    const float*  __restrict__ W1,     // [512, 3] row-major
    const float*  __restrict__ b1,
    const float*  __restrict__ gamma,
    const float*  __restrict__ beta,
    float4*       __restrict__ out4)   // [ntok, 256] float4
{
    const int pos = blockIdx.x;
    const int tid = threadIdx.x;           // 128 threads, dims 4*tid..4*tid+3
    const int cnt = g_count[pos];
    const int off = g_offset[pos];
    if (cnt == 0) return;

    // --- lattice features (scalar, per block) ---
    int level = 0;
#pragma unroll
    for (int i = 0; i < SPINE_N; i++) level += (c_spine[i] <= pos) ? 1 : 0;
    const float left  = (float)(pos - c_spine[level - 1]);
    const float right = (level < SPINE_N) ? (float)(c_spine[level] - pos) : 0.0f;
    const float lv    = (float)level;

    // --- h = feats @ W1^T + b1, dims 4*tid..4*tid+3 ---
    float h[4];
    float lsum = 0.0f;
#pragma unroll
    for (int k = 0; k < 4; k++) {
        const int d = 4 * tid + k;
        h[k] = fmaf(__ldg(&W1[d * 3 + 0]), left,
               fmaf(__ldg(&W1[d * 3 + 1]), right,
               fmaf(__ldg(&W1[d * 3 + 2]), lv, __ldg(&b1[d]))));
        lsum += h[k];
    }

    // --- block LayerNorm (mean, then two-pass variance) ---
    __shared__ float sred[4];
#pragma unroll
    for (int o = 16; o > 0; o >>= 1) lsum += __shfl_xor_sync(0xffffffffu, lsum, o);
    if ((tid & 31) == 0) sred[tid >> 5] = lsum;
    __syncthreads();
    const float mu = (sred[0] + sred[1] + sred[2] + sred[3]) * (1.0f / (float)D_HALF);

    float vs = 0.0f;
#pragma unroll
    for (int k = 0; k < 4; k++) { const float dd = h[k] - mu; vs = fmaf(dd, dd, vs); }
    __syncthreads();
#pragma unroll
    for (int o = 16; o > 0; o >>= 1) vs += __shfl_xor_sync(0xffffffffu, vs, o);
    if ((tid & 31) == 0) sred[tid >> 5] = vs;
    __syncthreads();
    const float rstd = rsqrtf((sred[0] + sred[1] + sred[2] + sred[3]) *
                              (1.0f / (float)D_HALF) + 1e-5f);

    // --- gamma/beta + exact-erf GELU, packed as float4 ---
    float4 lat;
    {
        float g[4];
#pragma unroll
        for (int k = 0; k < 4; k++) {
            const int d = 4 * tid + k;
            const float x = fmaf((h[k] - mu) * rstd, __ldg(&gamma[d]), __ldg(&beta[d]));
            g[k] = 0.5f * x * (1.0f + erff(x * 0.70710678118654752440f));
        }
        lat = make_float4(g[0], g[1], g[2], g[3]);
    }

    // --- pe row (read once per position) ---
    const float4 pev = __ldg(&pe4[(size_t)pos * 128 + tid]);

    // --- stream row to every token with this position (avg ~16) ---
    int tok_next = g_bucket[off];  // block-uniform broadcast load
    for (int j = 0; j < cnt; j++) {
        const int tok = tok_next;
        if (j + 1 < cnt) tok_next = g_bucket[off + j + 1];
        float4* __restrict__ dst = out4 + (size_t)tok * 256;
        __stcs(dst + tid,       pev);
        __stcs(dst + 128 + tid, lat);
    }
}

extern "C" void kernel_launch(void* const* d_in, const int* in_sizes, int n_in,
                              void* d_out, int out_size)
{
    const int*   positions = (const int*)  d_in[0];
    const float* pe        = (const float*)d_in[1];
    const float* W1        = (const float*)d_in[2];
    const float* b1        = (const float*)d_in[3];
    const float* ln_gamma  = (const float*)d_in[4];
    const float* ln_beta   = (const float*)d_in[5];
    float* out = (float*)d_out;

    const int ntok = in_sizes[0];  // B*S = 131072

    zero_kernel<<<(NPOS + 255) / 256, 256>>>();
    hist_kernel<<<(ntok + 255) / 256, 256>>>(positions, ntok);
    scan_kernel<<<1, 1024>>>();
    scatter_kernel<<<(ntok + 255) / 256, 256>>>(positions, ntok);
    gather_kernel<<<NPOS, 128>>>((const float4*)pe, W1, b1, ln_gamma, ln_beta,
                                 (float4*)out);
}

// round 5
// speedup vs baseline: 1.2849x; 1.1349x over previous
#include <cuda_runtime.h>
#include <math.h>

#define D_HALF   512
#define NPOS     8192
#define SPINE_N  10
#define MAX_TOK  131072

__constant__ int c_spine[SPINE_N] = {0, 2, 4, 12, 36, 104, 304, 888, 2592, 7568};

// Per-position token linked lists (device globals: no allocation allowed).
__device__ int g_head[NPOS];     // memset to -1 each call
__device__ int g_next[MAX_TOK];

// Single pass: push each token onto its position's list.
__global__ void __launch_bounds__(256) build_kernel(
    const int* __restrict__ positions, int ntok)
{
    const int i = blockIdx.x * blockDim.x + threadIdx.x;
    if (i < ntok) {
        const int pos = positions[i];
        const int old = atomicExch(&g_head[pos], i);
        g_next[i] = old;
    }
}

// One block per position: compute lat-enc row ONCE in registers
// (Linear(3,512) -> LayerNorm -> exact GELU), load pe row once, then walk the
// token list streaming the concatenated 4 KB row to each token's output slot.
__global__ void __launch_bounds__(128) gather_kernel(
    const float4* __restrict__ pe4,    // [NPOS, 128] float4
    const float*  __restrict__ W1,     // [512, 3] row-major
    const float*  __restrict__ b1,
    const float*  __restrict__ gamma,
    const float*  __restrict__ beta,
    float4*       __restrict__ out4)   // [ntok, 256] float4
{
    const int pos = blockIdx.x;
    const int tid = threadIdx.x;       // 128 threads, dims 4*tid..4*tid+3

    int tok = g_head[pos];             // block-uniform broadcast
    if (tok < 0) return;               // no tokens with this position

    // --- lattice features (scalar, per block) ---
    int level = 0;
#pragma unroll
    for (int i = 0; i < SPINE_N; i++) level += (c_spine[i] <= pos) ? 1 : 0;
    const float left  = (float)(pos - c_spine[level - 1]);
    const float right = (level < SPINE_N) ? (float)(c_spine[level] - pos) : 0.0f;
    const float lv    = (float)level;

    // --- h = feats @ W1^T + b1, dims 4*tid..4*tid+3 ---
    float h[4];
    float lsum = 0.0f;
#pragma unroll
    for (int k = 0; k < 4; k++) {
        const int d = 4 * tid + k;
        h[k] = fmaf(__ldg(&W1[d * 3 + 0]), left,
               fmaf(__ldg(&W1[d * 3 + 1]), right,
               fmaf(__ldg(&W1[d * 3 + 2]), lv, __ldg(&b1[d]))));
        lsum += h[k];
    }

    // --- block LayerNorm (mean, then two-pass variance) ---
    __shared__ float sred[4];
#pragma unroll
    for (int o = 16; o > 0; o >>= 1) lsum += __shfl_xor_sync(0xffffffffu, lsum, o);
    if ((tid & 31) == 0) sred[tid >> 5] = lsum;
    __syncthreads();
    const float mu = (sred[0] + sred[1] + sred[2] + sred[3]) * (1.0f / (float)D_HALF);

    float vs = 0.0f;
#pragma unroll
    for (int k = 0; k < 4; k++) { const float dd = h[k] - mu; vs = fmaf(dd, dd, vs); }
    __syncthreads();
#pragma unroll
    for (int o = 16; o > 0; o >>= 1) vs += __shfl_xor_sync(0xffffffffu, vs, o);
    if ((tid & 31) == 0) sred[tid >> 5] = vs;
    __syncthreads();
    const float rstd = rsqrtf((sred[0] + sred[1] + sred[2] + sred[3]) *
                              (1.0f / (float)D_HALF) + 1e-5f);

    // --- gamma/beta + exact-erf GELU, packed as float4 ---
    float4 lat;
    {
        float g[4];
#pragma unroll
        for (int k = 0; k < 4; k++) {
            const int d = 4 * tid + k;
            const float x = fmaf((h[k] - mu) * rstd, __ldg(&gamma[d]), __ldg(&beta[d]));
            g[k] = 0.5f * x * (1.0f + erff(x * 0.70710678118654752440f));
        }
        lat = make_float4(g[0], g[1], g[2], g[3]);
    }

    // --- pe row (read once per position) ---
    const float4 pev = __ldg(&pe4[(size_t)pos * 128 + tid]);

    // --- walk the list, streaming the row to each token (avg ~16) ---
    // Issue the next-pointer load BEFORE the stores so the L2 hop overlaps
    // the 8 KB of streaming stores for the current token.
    while (tok >= 0) {
        const int nxt = g_next[tok];   // broadcast L2 hit
        float4* __restrict__ dst = out4 + (size_t)tok * 256;
        __stcs(dst + tid,       pev);
        __stcs(dst + 128 + tid, lat);
        tok = nxt;
    }
}

extern "C" void kernel_launch(void* const* d_in, const int* in_sizes, int n_in,
                              void* d_out, int out_size)
{
    const int*   positions = (const int*)  d_in[0];
    const float* pe        = (const float*)d_in[1];
    const float* W1        = (const float*)d_in[2];
    const float* b1        = (const float*)d_in[3];
    const float* ln_gamma  = (const float*)d_in[4];
    const float* ln_beta   = (const float*)d_in[5];
    float* out = (float*)d_out;

    const int ntok = in_sizes[0];  // B*S = 131072

    void* head_ptr = nullptr;
    cudaGetSymbolAddress(&head_ptr, g_head);
    cudaMemsetAsync(head_ptr, 0xFF, NPOS * sizeof(int));  // heads = -1

    build_kernel<<<(ntok + 255) / 256, 256>>>(positions, ntok);

    gather_kernel<<<NPOS, 128>>>((const float4*)pe, W1, b1, ln_gamma, ln_beta,
                                 (float4*)out);
}